// round 17
// baseline (speedup 1.0000x reference)
#include <cuda_runtime.h>
#include <cuda_fp16.h>
#include <cstdint>

#define BHN 16
#define SEQ 4096
#define HD 64
#define BM 128
#define BN 64
#define NTHREADS 128
#define KPITCH 72   // smem row pitch in halves (144B rows -> conflict-free LDSM)
#define NT (SEQ / BN)
#define SPLIT 2
#define HT (NT / SPLIT)   // key-tiles per pass-B CTA
#define KS 4
#define RT (NT / KS)      // key-tiles per rowsum CTA
#define BMA 256           // rowsum rows per CTA (4 warps x 64 rows)
#define RF 4              // rowsum 16-row fragments per warp

// fp16 scratch copies of K and V (converted once per launch)
__device__ __half2 Ksc[BHN * SEQ * HD / 2];
__device__ __half2 Vsc[BHN * SEQ * HD / 2];
// rowsum partials and combined -log2(rowsum)
__device__ float RsP[KS * BHN * SEQ];
__device__ float LinvG[BHN * SEQ];
// partial O per key-split (fp16)
__device__ __half OPart[(size_t)SPLIT * BHN * SEQ * HD];

__device__ __forceinline__ float ex2f(float x) {
    float y;
    asm("ex2.approx.f32 %0, %1;" : "=f"(y) : "f"(x));
    return y;
}

__device__ __forceinline__ uint32_t h2ex2(uint32_t x) {
    uint32_t y;
    asm("ex2.approx.f16x2 %0, %1;" : "=r"(y) : "r"(x));
    return y;
}

__device__ __forceinline__ uint32_t packh2(float a, float b) {
    __half2 t = __floats2half2_rn(a, b);
    return reinterpret_cast<uint32_t&>(t);
}

__device__ __forceinline__ float2 unpackh2(uint32_t v) {
    return __half22float2(reinterpret_cast<__half2&>(v));
}

__device__ __forceinline__ uint32_t hadd2u(uint32_t a, uint32_t b) {
    __half2 r = __hadd2(reinterpret_cast<__half2&>(a), reinterpret_cast<__half2&>(b));
    return reinterpret_cast<uint32_t&>(r);
}

__device__ __forceinline__ void mma16816(float c[4], const uint32_t a[4],
                                         uint32_t b0, uint32_t b1) {
    asm volatile(
        "mma.sync.aligned.m16n8k16.row.col.f32.f16.f16.f32 "
        "{%0,%1,%2,%3},{%4,%5,%6,%7},{%8,%9},{%0,%1,%2,%3};"
        : "+f"(c[0]), "+f"(c[1]), "+f"(c[2]), "+f"(c[3])
        : "r"(a[0]), "r"(a[1]), "r"(a[2]), "r"(a[3]), "r"(b0), "r"(b1));
}

__device__ __forceinline__ void mma16816h(uint32_t c[2], const uint32_t a[4],
                                          uint32_t b0, uint32_t b1) {
    asm volatile(
        "mma.sync.aligned.m16n8k16.row.col.f16.f16.f16.f16 "
        "{%0,%1},{%2,%3,%4,%5},{%6,%7},{%0,%1};"
        : "+r"(c[0]), "+r"(c[1])
        : "r"(a[0]), "r"(a[1]), "r"(a[2]), "r"(a[3]), "r"(b0), "r"(b1));
}

__device__ __forceinline__ void ldsm_x4(uint32_t& r0, uint32_t& r1, uint32_t& r2,
                                        uint32_t& r3, uint32_t addr) {
    asm volatile("ldmatrix.sync.aligned.m8n8.x4.shared.b16 {%0,%1,%2,%3},[%4];"
                 : "=r"(r0), "=r"(r1), "=r"(r2), "=r"(r3) : "r"(addr));
}

__device__ __forceinline__ void ldsm_x4_t(uint32_t& r0, uint32_t& r1, uint32_t& r2,
                                          uint32_t& r3, uint32_t addr) {
    asm volatile("ldmatrix.sync.aligned.m8n8.x4.trans.shared.b16 {%0,%1,%2,%3},[%4];"
                 : "=r"(r0), "=r"(r1), "=r"(r2), "=r"(r3) : "r"(addr));
}

__device__ __forceinline__ void cpasync16(uint32_t dst, const void* src) {
    asm volatile("cp.async.cg.shared.global [%0],[%1],16;" :: "r"(dst), "l"(src));
}
__device__ __forceinline__ void cp_commit() {
    asm volatile("cp.async.commit_group;");
}
template <int N>
__device__ __forceinline__ void cp_wait() {
    asm volatile("cp.async.wait_group %0;" :: "n"(N));
}

// prefetch one [BN x HD] fp16 tile, rows permuted within each 16-key group.
__device__ __forceinline__ void prefetch_tile(uint32_t dstbase, const __half* src,
                                              int tid) {
#pragma unroll
    for (int t = 0; t < 4; ++t) {
        int i = tid + t * NTHREADS;
        int r = i >> 3;
        int c8 = (i & 7) << 3;
        int s = r & 15;
        int a = ((s & 6) << 1) | ((s & 8) >> 2) | (s & 1);
        int srcr = (r & 48) | a;
        cpasync16(dstbase + (uint32_t)((r * KPITCH + c8) * 2), src + srcr * HD + c8);
    }
}

// ---------------- pre-conversion kernel ----------------
__global__ void __launch_bounds__(256)
convert_kernel(const float* __restrict__ K, const float* __restrict__ V) {
    const int n4 = BHN * SEQ * HD / 4;
    int i = blockIdx.x * blockDim.x + threadIdx.x;
    if (i < n4) {
        float4 f = reinterpret_cast<const float4*>(K)[i];
        Ksc[2 * i] = __floats2half2_rn(f.x, f.y);
        Ksc[2 * i + 1] = __floats2half2_rn(f.z, f.w);
    } else {
        int j = i - n4;
        float4 f = reinterpret_cast<const float4*>(V)[j];
        Vsc[2 * j] = __floats2half2_rn(f.x, f.y);
        Vsc[2 * j + 1] = __floats2half2_rn(f.z, f.w);
    }
}

// ------- PASS A kernel: partial row sums, KS=4 key-split, 64 rows/warp --------
__global__ void __launch_bounds__(NTHREADS, 4)
rowsum_kernel(const float* __restrict__ Qg) {
    __shared__ __half Kb[2][BN * KPITCH];

    const int bh = blockIdx.y;
    const int kz = blockIdx.z;
    const float* Qb = Qg + (size_t)bh * SEQ * HD;
    const __half* Kb16 = reinterpret_cast<const __half*>(Ksc) + (size_t)bh * SEQ * HD +
                         (size_t)kz * RT * BN * HD;

    const int tid = threadIdx.x;
    const int warp = tid >> 5;
    const int lane = tid & 31;
    const int g = lane >> 2;
    const int qq = lane & 3;
    const int row0 = blockIdx.x * BMA + warp * (16 * RF);

    const uint32_t bK0 = (uint32_t)__cvta_generic_to_shared(&Kb[0][0]);
    const uint32_t bK1 = (uint32_t)__cvta_generic_to_shared(&Kb[1][0]);

    const int qk_r = (lane & 7) + ((lane & 16) ? 8 : 0);
    const int qk_c = (lane & 8) ? 8 : 0;
    const uint32_t offK = (uint32_t)((qk_r * KPITCH + qk_c) * 2);
    const uint32_t NPOFF = 16 * KPITCH * 2;

    const float SC = 0.1803368801111244f;

    uint32_t qh[RF][4][4];
#pragma unroll
    for (int rf = 0; rf < RF; ++rf)
#pragma unroll
        for (int kc = 0; kc < 4; ++kc)
#pragma unroll
            for (int p = 0; p < 4; ++p) {
                int r = row0 + rf * 16 + g + (p & 1) * 8;
                int d = kc * 16 + (p >> 1) * 8 + qq * 2;
                float2 f = *reinterpret_cast<const float2*>(Qb + (size_t)r * HD + d);
                qh[rf][kc][p] = packh2(f.x * SC, f.y * SC);
            }

    float rs[RF][2] = {};
    prefetch_tile(bK0, Kb16, tid);
    cp_commit();
    for (int kt = 0; kt < RT; ++kt) {
        if (kt + 1 < RT) {
            prefetch_tile((kt & 1) ? bK0 : bK1, Kb16 + (size_t)(kt + 1) * BN * HD, tid);
            cp_commit();
            cp_wait<1>();
        } else {
            cp_wait<0>();
        }
        __syncthreads();
        const uint32_t aK = ((kt & 1) ? bK1 : bK0) + offK;
        uint32_t acc[RF][2] = {};
#pragma unroll
        for (int np = 0; np < 4; ++np) {
            uint32_t h[4][4];
#pragma unroll
            for (int kc = 0; kc < 4; ++kc)
                ldsm_x4(h[kc][0], h[kc][1], h[kc][2], h[kc][3],
                        aK + np * NPOFF + kc * 32);
#pragma unroll
            for (int rf = 0; rf < RF; ++rf) {
                uint32_t ca[2] = {0, 0}, cb[2] = {0, 0};
#pragma unroll
                for (int kc = 0; kc < 4; ++kc) {
                    mma16816h(ca, qh[rf][kc], h[kc][0], h[kc][1]);
                    mma16816h(cb, qh[rf][kc], h[kc][2], h[kc][3]);
                }
                acc[rf][0] = hadd2u(acc[rf][0], hadd2u(h2ex2(ca[0]), h2ex2(cb[0])));
                acc[rf][1] = hadd2u(acc[rf][1], hadd2u(h2ex2(ca[1]), h2ex2(cb[1])));
            }
        }
#pragma unroll
        for (int rf = 0; rf < RF; ++rf) {
            float2 f0 = unpackh2(acc[rf][0]);
            float2 f1 = unpackh2(acc[rf][1]);
            rs[rf][0] += f0.x + f0.y;
            rs[rf][1] += f1.x + f1.y;
        }
        __syncthreads();
    }
#pragma unroll
    for (int rf = 0; rf < RF; ++rf)
#pragma unroll
        for (int h = 0; h < 2; ++h) {
            float v = rs[rf][h];
            v += __shfl_xor_sync(0xffffffffu, v, 1);
            v += __shfl_xor_sync(0xffffffffu, v, 2);
            if (qq == 0)
                RsP[((size_t)kz * BHN + bh) * SEQ + row0 + rf * 16 + g + h * 8] = v;
        }
}

// ------------- combine KS partial rowsums into -log2(rowsum), fixed order -----
__global__ void __launch_bounds__(256)
linv_kernel() {
    const int n = BHN * SEQ;
    int i = blockIdx.x * blockDim.x + threadIdx.x;
    if (i < n) {
        float s = RsP[i];
#pragma unroll
        for (int p = 1; p < KS; ++p) s += RsP[i + p * n];
        LinvG[i] = -__log2f(s);
    }
}

// ---------------- PASS B kernel: key-split halves, coalesced fp16 stores ------
__global__ void __launch_bounds__(NTHREADS, 3)
attn_kernel(const float* __restrict__ Qg, float* __restrict__ out) {
    __shared__ __half Kb[2][BN * KPITCH];
    __shared__ __half Vb[2][BN * KPITCH];

    const int bh = blockIdx.y;
    const int kz = blockIdx.z;          // key-split index
    const int kt0 = kz * HT;
    const float* Qb = Qg + (size_t)bh * SEQ * HD;
    const __half* Kb16 = reinterpret_cast<const __half*>(Ksc) + (size_t)bh * SEQ * HD +
                         (size_t)kt0 * BN * HD;
    const __half* Vb16 = reinterpret_cast<const __half*>(Vsc) + (size_t)bh * SEQ * HD +
                         (size_t)kt0 * BN * HD;
    __half* OPb = OPart + ((size_t)kz * BHN + bh) * SEQ * HD;
    float* Ab = out + (size_t)BHN * SEQ * HD + (size_t)bh * SEQ * SEQ;

    const int tid = threadIdx.x;
    const int warp = tid >> 5;
    const int lane = tid & 31;
    const int g = lane >> 2;
    const int qq = lane & 3;
    const int row0 = blockIdx.x * BM + warp * 32;

    const uint32_t bK0 = (uint32_t)__cvta_generic_to_shared(&Kb[0][0]);
    const uint32_t bK1 = (uint32_t)__cvta_generic_to_shared(&Kb[1][0]);
    const uint32_t bV0 = (uint32_t)__cvta_generic_to_shared(&Vb[0][0]);
    const uint32_t bV1 = (uint32_t)__cvta_generic_to_shared(&Vb[1][0]);

    const int qk_r = (lane & 7) + ((lane & 16) ? 8 : 0);
    const int qk_c = (lane & 8) ? 8 : 0;
    const uint32_t offK = (uint32_t)((qk_r * KPITCH + qk_c) * 2);
    const int v_r = (lane & 7) + ((lane & 8) ? 8 : 0);
    const int v_c = (lane & 16) ? 8 : 0;
    const uint32_t offV = (uint32_t)((v_r * KPITCH + v_c) * 2);
    const uint32_t NPOFF = 16 * KPITCH * 2;

    // store-transpose lane constants
    const int srcBase = 4 * (lane >> 3) + (lane & 3);
    const bool npSel = (lane >> 2) & 1;
    const int cOff = 4 * (lane & 7);

    const float SC = 0.1803368801111244f;

    uint32_t qh[2][4][4];
#pragma unroll
    for (int rf = 0; rf < 2; ++rf)
#pragma unroll
        for (int kc = 0; kc < 4; ++kc)
#pragma unroll
            for (int p = 0; p < 4; ++p) {
                int r = row0 + rf * 16 + g + (p & 1) * 8;
                int d = kc * 16 + (p >> 1) * 8 + qq * 2;
                float2 f = *reinterpret_cast<const float2*>(Qb + (size_t)r * HD + d);
                qh[rf][kc][p] = packh2(f.x * SC, f.y * SC);
            }

    float linv[2][2];
#pragma unroll
    for (int rf = 0; rf < 2; ++rf)
#pragma unroll
        for (int h = 0; h < 2; ++h)
            linv[rf][h] = LinvG[bh * SEQ + row0 + rf * 16 + g + h * 8];

    float o[2][8][4] = {};
    prefetch_tile(bK0, Kb16, tid);
    prefetch_tile(bV0, Vb16, tid);
    cp_commit();
    for (int kt = 0; kt < HT; ++kt) {
        if (kt + 1 < HT) {
            const uint32_t dK = (kt & 1) ? bK0 : bK1;
            const uint32_t dV = (kt & 1) ? bV0 : bV1;
            prefetch_tile(dK, Kb16 + (size_t)(kt + 1) * BN * HD, tid);
            prefetch_tile(dV, Vb16 + (size_t)(kt + 1) * BN * HD, tid);
            cp_commit();
            cp_wait<1>();
        } else {
            cp_wait<0>();
        }
        __syncthreads();
        const uint32_t aK = ((kt & 1) ? bK1 : bK0) + offK;
        const uint32_t aV = ((kt & 1) ? bV1 : bV0) + offV;

        uint32_t ahP[2][2][4];   // packed fp16 P for the current np-pair
#pragma unroll
        for (int np = 0; np < 4; ++np) {
            uint32_t h[4][4];
#pragma unroll
            for (int kc = 0; kc < 4; ++kc)
                ldsm_x4(h[kc][0], h[kc][1], h[kc][2], h[kc][3],
                        aK + np * NPOFF + kc * 32);
            float ca[2][4] = {}, cb[2][4] = {};
#pragma unroll
            for (int rf = 0; rf < 2; ++rf)
#pragma unroll
                for (int kc = 0; kc < 4; ++kc) {
                    mma16816(ca[rf], qh[rf][kc], h[kc][0], h[kc][1]);
                    mma16816(cb[rf], qh[rf][kc], h[kc][2], h[kc][3]);
                }

#pragma unroll
            for (int rf = 0; rf < 2; ++rf) {
                const float l0 = linv[rf][0], l1 = linv[rf][1];
                ca[rf][0] = ex2f(ca[rf][0] + l0);
                ca[rf][1] = ex2f(ca[rf][1] + l0);
                ca[rf][2] = ex2f(ca[rf][2] + l1);
                ca[rf][3] = ex2f(ca[rf][3] + l1);
                cb[rf][0] = ex2f(cb[rf][0] + l0);
                cb[rf][1] = ex2f(cb[rf][1] + l0);
                cb[rf][2] = ex2f(cb[rf][2] + l1);
                cb[rf][3] = ex2f(cb[rf][3] + l1);
                ahP[np & 1][rf][0] = packh2(ca[rf][0], ca[rf][1]);
                ahP[np & 1][rf][1] = packh2(ca[rf][2], ca[rf][3]);
                ahP[np & 1][rf][2] = packh2(cb[rf][0], cb[rf][1]);
                ahP[np & 1][rf][3] = packh2(cb[rf][2], cb[rf][3]);
            }

            // AV for this 16-key group over all 64 output columns
#pragma unroll
            for (int nd = 0; nd < 4; ++nd) {
                uint32_t v0, v1, v2, v3;
                ldsm_x4_t(v0, v1, v2, v3, aV + np * NPOFF + nd * 32);
#pragma unroll
                for (int rf = 0; rf < 2; ++rf) {
                    mma16816(o[rf][2 * nd], ahP[np & 1][rf], v0, v1);
                    mma16816(o[rf][2 * nd + 1], ahP[np & 1][rf], v2, v3);
                }
            }

            // after each odd np: coalesced transpose-store of the np-pair
            if (np & 1) {
                const int C = np >> 1;
                float* colbase = Ab + (kt0 + kt) * BN + 32 * C + cOff;
#pragma unroll
                for (int rf = 0; rf < 2; ++rf)
#pragma unroll
                    for (int hh = 0; hh < 2; ++hh)
#pragma unroll
                        for (int a = 0; a < 2; ++a) {
                            int src = srcBase + 16 * a;
                            uint32_t t0A = __shfl_sync(0xffffffffu, ahP[0][rf][hh], src);
                            uint32_t t0B = __shfl_sync(0xffffffffu, ahP[1][rf][hh], src);
                            uint32_t t1A = __shfl_sync(0xffffffffu, ahP[0][rf][hh + 2], src);
                            uint32_t t1B = __shfl_sync(0xffffffffu, ahP[1][rf][hh + 2], src);
                            uint32_t w0 = npSel ? t0B : t0A;
                            uint32_t w1 = npSel ? t1B : t1A;
                            float2 fa = unpackh2(w0);
                            float2 fb = unpackh2(w1);
                            int grow = row0 + 16 * rf + 8 * hh + 4 * a + (lane >> 3);
                            __stcs(reinterpret_cast<float4*>(colbase + (size_t)grow * SEQ),
                                   make_float4(fa.x, fa.y, fb.x, fb.y));
                        }
            }
        }
        __syncthreads();
    }

    // ---- write partial O (fp16) ----
#pragma unroll
    for (int rf = 0; rf < 2; ++rf)
#pragma unroll
        for (int nt = 0; nt < 8; ++nt) {
            int col = nt * 8 + qq * 2;
            int r = row0 + rf * 16 + g;
            *reinterpret_cast<uint32_t*>(OPb + (size_t)r * HD + col) =
                packh2(o[rf][nt][0], o[rf][nt][1]);
            *reinterpret_cast<uint32_t*>(OPb + (size_t)(r + 8) * HD + col) =
                packh2(o[rf][nt][2], o[rf][nt][3]);
        }
}

// ------ O reduce: O = sum of SPLIT fp16 partials in fp32, fixed order ---------
__global__ void __launch_bounds__(256)
reduce_kernel(float* __restrict__ out) {
    const int n4h = BHN * SEQ * HD / 4;   // uint2 elements (4 halves each)
    int i = blockIdx.x * blockDim.x + threadIdx.x;
    if (i < n4h) {
        const uint2* a = reinterpret_cast<const uint2*>(OPart);
        uint2 x = a[i];
        float2 s0 = unpackh2(x.x);
        float2 s1 = unpackh2(x.y);
#pragma unroll
        for (int p = 1; p < SPLIT; ++p) {
            uint2 y = a[i + (size_t)p * n4h];
            float2 y0 = unpackh2(y.x);
            float2 y1 = unpackh2(y.y);
            s0.x += y0.x; s0.y += y0.y;
            s1.x += y1.x; s1.y += y1.y;
        }
        reinterpret_cast<float4*>(out)[i] = make_float4(s0.x, s0.y, s1.x, s1.y);
    }
}

extern "C" void kernel_launch(void* const* d_in, const int* in_sizes, int n_in,
                              void* d_out, int out_size) {
    const float* q = (const float*)d_in[0];
    const float* k = (const float*)d_in[1];
    const float* v = (const float*)d_in[2];
    (void)in_sizes; (void)n_in; (void)out_size;
    const int n4 = BHN * SEQ * HD / 4;
    convert_kernel<<<(2 * n4) / 256, 256>>>(k, v);
    dim3 gridA(SEQ / BMA, BHN, KS);
    rowsum_kernel<<<gridA, NTHREADS>>>(q);
    linv_kernel<<<(BHN * SEQ + 255) / 256, 256>>>();
    dim3 gridB(SEQ / BM, BHN, SPLIT);
    attn_kernel<<<gridB, NTHREADS>>>(q, (float*)d_out);
    reduce_kernel<<<(n4 + 255) / 256, 256>>>((float*)d_out);
}